// round 4
// baseline (speedup 1.0000x reference)
#include <cuda_runtime.h>
#include <cstdint>
#include <math.h>

#define FULLMASK 0xffffffffu

// Problem constants
#define NB   256   // batch
#define NV   512   // num vars
#define NE   32    // embed dim
#define NIN  512   // in dim
#define NK   10    // top-k

// Scratch (device globals — no allocation allowed)
__device__ float g_c2[NB * NE];
__device__ float g_gate[NB];

// ---------------- packed f32x2 helpers (ptxas won't auto-fuse; PTX only) ----
__device__ __forceinline__ unsigned long long mul2(unsigned long long a,
                                                   unsigned long long b) {
    unsigned long long r;
    asm("mul.rn.f32x2 %0, %1, %2;" : "=l"(r) : "l"(a), "l"(b));
    return r;
}
__device__ __forceinline__ unsigned long long fma2(unsigned long long a,
                                                   unsigned long long b,
                                                   unsigned long long c) {
    unsigned long long r;
    asm("fma.rn.f32x2 %0, %1, %2, %3;" : "=l"(r) : "l"(a), "l"(b), "l"(c));
    return r;
}
__device__ __forceinline__ float hsum2(unsigned long long a) {
    float lo, hi;
    asm("mov.b64 {%0,%1}, %2;" : "=f"(lo), "=f"(hi) : "l"(a));
    return lo + hi;
}

// order-preserving float->uint key (monotone: a<b  <=>  key(a)<key(b))
__device__ __forceinline__ unsigned f2key(float f) {
    unsigned b = __float_as_uint(f);
    return b ^ ((unsigned)(((int)b) >> 31) | 0x80000000u);
}
__device__ __forceinline__ float key2f(unsigned k) {
    unsigned b = (k & 0x80000000u) ? (k ^ 0x80000000u) : ~k;
    return __uint_as_float(b);
}

// ---------------- Kernel 1: context MLP -> c2[b,e], gate[b] -----------------
// grid = 256 (one block per batch), block = 128
__global__ void mlp_kernel(const float* __restrict__ ctx,
                           const float* __restrict__ W1,
                           const float* __restrict__ b1,
                           const float* __restrict__ W2,
                           const float* __restrict__ b2,
                           const float* __restrict__ Wg,
                           const float* __restrict__ bg) {
    __shared__ float x_sh[NIN];
    __shared__ float h_sh[NE];
    int b   = blockIdx.x;
    int tid = threadIdx.x;

    ((float4*)x_sh)[tid] = ((const float4*)(ctx + b * NIN))[tid];
    __syncthreads();

    int e = tid >> 2, p = tid & 3;
    const float4* wrow = (const float4*)(W1 + e * NIN + p * 128);
    const float4* xrow = (const float4*)(x_sh + p * 128);
    float acc = 0.f;
#pragma unroll
    for (int q = 0; q < 32; ++q) {
        float4 wv = wrow[q];
        float4 xv = xrow[q];
        acc += wv.x * xv.x + wv.y * xv.y + wv.z * xv.z + wv.w * xv.w;
    }
    acc += __shfl_xor_sync(FULLMASK, acc, 1);
    acc += __shfl_xor_sync(FULLMASK, acc, 2);
    if (p == 0) h_sh[e] = fmaxf(acc + b1[e], 0.f);
    __syncthreads();

    if (tid < NE) {
        float cv = b2[tid];
#pragma unroll
        for (int f = 0; f < NE; ++f) cv += h_sh[f] * W2[tid * NE + f];
        g_c2[b * NE + tid] = cv * cv;
        float gp = cv * Wg[tid];
#pragma unroll
        for (int o = 16; o; o >>= 1) gp += __shfl_xor_sync(FULLMASK, gp, o);
        if (tid == 0) g_gate[b] = 1.f / (1.f + expf(-(gp + bg[0])));
    }
}

// ---------------- Kernel 2: scores + top-k mask + sigmoid + gate ------------
// grid = 2048 (8 blocks per batch, 64 rows each), block = 256 (8 warps)
// One warp per row i: lane owns j = k*32+lane for k in [0,16).
// Score accumulation is kept bit-identical to the R2-passing kernel
// (same f32x2 accumulators, same reduction order) to preserve the top-k
// flip set (rel_err margin vs 1e-3 is only ~1.5x).
__global__ void __launch_bounds__(256, 2)
adj_kernel(const float* __restrict__ emb, float* __restrict__ out) {
    extern __shared__ char smem_raw[];
    __shared__ float4 c2s4[8];
    __shared__ float  gate_s;

    int tid  = threadIdx.x;
    int lane = tid & 31;
    int w    = tid >> 5;
    int b    = blockIdx.x >> 3;
    int ibase = (blockIdx.x & 7) << 6;

    // stage emb (512 rows x 8 float4), float4-slot XOR swizzle (q ^ (j&7))
    const float4* eg = (const float4*)emb;
    float4* es = (float4*)smem_raw;
#pragma unroll
    for (int t = 0; t < 16; ++t) {
        int idx = tid + (t << 8);
        int j = idx >> 3, q = idx & 7;
        es[(j << 3) | (q ^ (j & 7))] = eg[idx];
    }
    if (tid < 8)  c2s4[tid] = ((const float4*)(g_c2 + (b << 5)))[tid];
    if (tid == 0) gate_s = g_gate[b];
    __syncthreads();

    float gate = gate_s;
    const char* smem_b = smem_raw;
    const ulonglong2* c2p = (const ulonglong2*)c2s4;

    // per-thread constant swizzle offsets (j&7 == lane&7 for j = k*32+lane)
    const int jsw = lane & 7;
    int joff[8];
#pragma unroll
    for (int q = 0; q < 8; ++q) joff[q] = ((q ^ jsw) << 4);

#pragma unroll 1   // keep one row's register set live at a time (regs!)
    for (int t = 0; t < 8; ++t) {
        int i = ibase + (w << 3) + t;

        // zi[e] = c2[e] * emb[i,e]   (packed as 16 f32x2)
        unsigned long long zi[16];
        {
            int isw = i & 7;
            const char* irow = smem_b + (i << 7);
#pragma unroll
            for (int q = 0; q < 8; ++q) {
                ulonglong2 ev = *(const ulonglong2*)(irow + ((q ^ isw) << 4));
                ulonglong2 cv = c2p[q];
                zi[2 * q]     = mul2(ev.x, cv.x);
                zi[2 * q + 1] = mul2(ev.y, cv.y);
            }
        }

        // scores for this lane's 16 columns -> order-preserving uint keys
        unsigned key[16];
#pragma unroll
        for (int k = 0; k < 16; ++k) {
            const char* jrow = smem_b + (((k << 5) | lane) << 7);
            unsigned long long a0 = 0ull, a1 = 0ull;
#pragma unroll
            for (int q = 0; q < 8; ++q) {
                ulonglong2 ev = *(const ulonglong2*)(jrow + joff[q]);
                a0 = fma2(ev.x, zi[2 * q],     a0);
                a1 = fma2(ev.y, zi[2 * q + 1], a1);
            }
            key[k] = f2key(hsum2(a0) + hsum2(a1));
        }

        // 10th-largest via REDUX.UMAX rounds; 4 groups of 4 per lane so the
        // per-round rescan touches only 4 values.
        unsigned g[4];
#pragma unroll
        for (int q = 0; q < 4; ++q) {
            unsigned m0 = max(key[4 * q],     key[4 * q + 1]);
            unsigned m1 = max(key[4 * q + 2], key[4 * q + 3]);
            g[q] = max(m0, m1);
        }
        unsigned lmax = max(max(g[0], g[1]), max(g[2], g[3]));
        unsigned m = lmax;
#pragma unroll 1
        for (int r = 0; r < NK; ++r) {
            m = __reduce_max_sync(FULLMASK, lmax);
            if (r == NK - 1) break;
            if (lmax == m) {
#pragma unroll
                for (int q = 0; q < 4; ++q) {
                    if (g[q] == m) {
                        unsigned nm = 0u;
#pragma unroll
                        for (int x = 0; x < 4; ++x) {
                            unsigned v = key[4 * q + x];
                            nm = max(nm, (v < m) ? v : 0u);
                        }
                        g[q] = nm;
                    }
                }
                lmax = max(max(g[0], g[1]), max(g[2], g[3]));
            }
        }
        unsigned thr = m;

        // masked sigmoid * gate; sigmoid only for kept (~10/row) entries
        float* orow = out + (((size_t)(b << 9) + (size_t)i) << 9);
#pragma unroll
        for (int k = 0; k < 16; ++k) {
            float v = 0.0f;
            if (key[k] >= thr) {
                float s = key2f(key[k]);
                v = gate / (1.0f + expf(-s));
            }
            orow[(k << 5) | lane] = v;  // fully coalesced: j = k*32 + lane
        }
    }
}

// ---------------------------------------------------------------------------
extern "C" void kernel_launch(void* const* d_in, const int* in_sizes, int n_in,
                              void* d_out, int out_size) {
    const float* ctx = (const float*)d_in[0];  // context_vec [256,512]
    const float* emb = (const float*)d_in[1];  // var_emb     [512,32]
    const float* W1  = (const float*)d_in[2];  // [32,512]
    const float* b1  = (const float*)d_in[3];  // [32]
    const float* W2  = (const float*)d_in[4];  // [32,32]
    const float* b2  = (const float*)d_in[5];  // [32]
    const float* Wg  = (const float*)d_in[6];  // [1,32]
    const float* bg  = (const float*)d_in[7];  // [1]
    float* out = (float*)d_out;

    cudaFuncSetAttribute(adj_kernel,
                         cudaFuncAttributeMaxDynamicSharedMemorySize, 65536);

    mlp_kernel<<<256, 128>>>(ctx, W1, b1, W2, b2, Wg, bg);
    adj_kernel<<<2048, 256, 65536>>>(emb, out);
}

// round 12
// speedup vs baseline: 1.5998x; 1.5998x over previous
#include <cuda_runtime.h>
#include <cstdint>
#include <math.h>

#define FULLMASK 0xffffffffu

// Problem constants
#define NB   256   // batch
#define NV   512   // num vars
#define NE   32    // embed dim
#define NIN  512   // in dim
#define NK   10    // top-k

// Scratch (device globals — no allocation allowed)
__device__ float g_c2[NB * NE];
__device__ float g_gate[NB];

// ---------------- packed f32x2 helpers (ptxas won't auto-fuse; PTX only) ----
__device__ __forceinline__ unsigned long long mul2(unsigned long long a,
                                                   unsigned long long b) {
    unsigned long long r;
    asm("mul.rn.f32x2 %0, %1, %2;" : "=l"(r) : "l"(a), "l"(b));
    return r;
}
__device__ __forceinline__ unsigned long long fma2(unsigned long long a,
                                                   unsigned long long b,
                                                   unsigned long long c) {
    unsigned long long r;
    asm("fma.rn.f32x2 %0, %1, %2, %3;" : "=l"(r) : "l"(a), "l"(b), "l"(c));
    return r;
}
__device__ __forceinline__ float hsum2(unsigned long long a) {
    float lo, hi;
    asm("mov.b64 {%0,%1}, %2;" : "=f"(lo), "=f"(hi) : "l"(a));
    return lo + hi;
}

// order-preserving float->uint key (monotone: a<b  <=>  key(a)<key(b))
__device__ __forceinline__ unsigned f2key(float f) {
    unsigned b = __float_as_uint(f);
    return b ^ ((unsigned)(((int)b) >> 31) | 0x80000000u);
}
__device__ __forceinline__ float key2f(unsigned k) {
    unsigned b = (k & 0x80000000u) ? (k ^ 0x80000000u) : ~k;
    return __uint_as_float(b);
}

// 10th-largest over the warp's 512 keys (16 per lane). ALL loops unrolled so
// every key[]/g[] index is a compile-time constant (never demote to local!).
__device__ __forceinline__ unsigned topk_thresh(const unsigned (&key)[16]) {
    unsigned g[4];
#pragma unroll
    for (int q = 0; q < 4; ++q) {
        unsigned m0 = max(key[4 * q],     key[4 * q + 1]);
        unsigned m1 = max(key[4 * q + 2], key[4 * q + 3]);
        g[q] = max(m0, m1);
    }
    unsigned lmax = max(max(g[0], g[1]), max(g[2], g[3]));
    unsigned m = lmax;
#pragma unroll 1
    for (int r = 0; r < NK; ++r) {
        m = __reduce_max_sync(FULLMASK, lmax);
        if (r == NK - 1) break;
        if (lmax == m) {
#pragma unroll
            for (int q = 0; q < 4; ++q) {
                if (g[q] == m) {
                    unsigned nm = 0u;
#pragma unroll
                    for (int x = 0; x < 4; ++x) {
                        unsigned v = key[4 * q + x];
                        nm = max(nm, (v < m) ? v : 0u);
                    }
                    g[q] = nm;
                }
            }
            lmax = max(max(g[0], g[1]), max(g[2], g[3]));
        }
    }
    return m;
}

// ---------------- Kernel 1: context MLP -> c2[b,e], gate[b] -----------------
// grid = 256 (one block per batch), block = 128
__global__ void mlp_kernel(const float* __restrict__ ctx,
                           const float* __restrict__ W1,
                           const float* __restrict__ b1,
                           const float* __restrict__ W2,
                           const float* __restrict__ b2,
                           const float* __restrict__ Wg,
                           const float* __restrict__ bg) {
    __shared__ float x_sh[NIN];
    __shared__ float h_sh[NE];
    int b   = blockIdx.x;
    int tid = threadIdx.x;

    ((float4*)x_sh)[tid] = ((const float4*)(ctx + b * NIN))[tid];
    __syncthreads();

    int e = tid >> 2, p = tid & 3;
    const float4* wrow = (const float4*)(W1 + e * NIN + p * 128);
    const float4* xrow = (const float4*)(x_sh + p * 128);
    float acc = 0.f;
#pragma unroll
    for (int q = 0; q < 32; ++q) {
        float4 wv = wrow[q];
        float4 xv = xrow[q];
        acc += wv.x * xv.x + wv.y * xv.y + wv.z * xv.z + wv.w * xv.w;
    }
    acc += __shfl_xor_sync(FULLMASK, acc, 1);
    acc += __shfl_xor_sync(FULLMASK, acc, 2);
    if (p == 0) h_sh[e] = fmaxf(acc + b1[e], 0.f);
    __syncthreads();

    if (tid < NE) {
        float cv = b2[tid];
#pragma unroll
        for (int f = 0; f < NE; ++f) cv += h_sh[f] * W2[tid * NE + f];
        g_c2[b * NE + tid] = cv * cv;
        float gp = cv * Wg[tid];
#pragma unroll
        for (int o = 16; o; o >>= 1) gp += __shfl_xor_sync(FULLMASK, gp, o);
        if (tid == 0) g_gate[b] = 1.f / (1.f + expf(-(gp + bg[0])));
    }
}

// ---------------- Kernel 2: scores + top-k mask + sigmoid + gate ------------
// grid = 4096 (16 blocks/batch, 32 rows each), block = 128 (4 warps).
// One warp processes 8 rows as 4 PAIRS: each j-side emb load (8 LDS.128)
// feeds FMAs for two i-rows, halving LDS issues/bytes vs 1 row at a time.
// smem (64KB) limits to 3 CTAs/SM if regs <= 170; NO launch_bounds cap, so
// ptxas never spills (the R3 failure). Score math is bit-identical to the
// R2-passing kernel (same accumulator split + op order) -> same flip set.
__global__ void adj_kernel(const float* __restrict__ emb,
                           float* __restrict__ out) {
    extern __shared__ char smem_raw[];
    __shared__ float4 c2s4[8];
    __shared__ float  gate_s;

    int tid  = threadIdx.x;
    int lane = tid & 31;
    int w    = tid >> 5;            // 0..3
    int b    = blockIdx.x >> 4;
    int ibase = (blockIdx.x & 15) << 5;   // 32 rows per CTA

    // stage emb (512 rows x 8 float4), float4-slot XOR swizzle (q ^ (j&7))
    const float4* eg = (const float4*)emb;
    float4* es = (float4*)smem_raw;
#pragma unroll
    for (int t = 0; t < 32; ++t) {
        int idx = tid + (t << 7);
        int j = idx >> 3, q = idx & 7;
        es[(j << 3) | (q ^ (j & 7))] = eg[idx];
    }
    if (tid < 8)  c2s4[tid] = ((const float4*)(g_c2 + (b << 5)))[tid];
    if (tid == 0) gate_s = g_gate[b];
    __syncthreads();

    float gate = gate_s;
    const char* smem_b = smem_raw;
    const ulonglong2* c2p = (const ulonglong2*)c2s4;

    // per-thread constant swizzle offsets (j&7 == lane&7 for j = k*32+lane)
    const int jsw = lane & 7;
    int joff[8];
#pragma unroll
    for (int q = 0; q < 8; ++q) joff[q] = ((q ^ jsw) << 4);

#pragma unroll 1   // one row-PAIR of registers live at a time
    for (int t = 0; t < 4; ++t) {
        int i0 = ibase + (w << 3) + (t << 1);
        int i1 = i0 + 1;

        // zi[e] = c2[e] * emb[i,e] for both rows (16 f32x2 each)
        unsigned long long zi0[16], zi1[16];
        {
            int isw0 = i0 & 7, isw1 = i1 & 7;
            const char* ir0 = smem_b + (i0 << 7);
            const char* ir1 = smem_b + (i1 << 7);
#pragma unroll
            for (int q = 0; q < 8; ++q) {
                ulonglong2 cv = c2p[q];
                ulonglong2 e0 = *(const ulonglong2*)(ir0 + ((q ^ isw0) << 4));
                zi0[2 * q]     = mul2(e0.x, cv.x);
                zi0[2 * q + 1] = mul2(e0.y, cv.y);
                ulonglong2 e1 = *(const ulonglong2*)(ir1 + ((q ^ isw1) << 4));
                zi1[2 * q]     = mul2(e1.x, cv.x);
                zi1[2 * q + 1] = mul2(e1.y, cv.y);
            }
        }

        // scores: each ev load serves BOTH rows
        unsigned key0[16], key1[16];
#pragma unroll
        for (int k = 0; k < 16; ++k) {
            const char* jrow = smem_b + (((k << 5) | lane) << 7);
            unsigned long long a0 = 0ull, a1 = 0ull;   // row i0
            unsigned long long b0 = 0ull, b1 = 0ull;   // row i1
#pragma unroll
            for (int q = 0; q < 8; ++q) {
                ulonglong2 ev = *(const ulonglong2*)(jrow + joff[q]);
                a0 = fma2(ev.x, zi0[2 * q],     a0);
                a1 = fma2(ev.y, zi0[2 * q + 1], a1);
                b0 = fma2(ev.x, zi1[2 * q],     b0);
                b1 = fma2(ev.y, zi1[2 * q + 1], b1);
            }
            key0[k] = f2key(hsum2(a0) + hsum2(a1));
            key1[k] = f2key(hsum2(b0) + hsum2(b1));
        }

        unsigned thr0 = topk_thresh(key0);
        unsigned thr1 = topk_thresh(key1);

        // masked sigmoid * gate; sigmoid only for kept (~10/row) entries
        float* or0 = out + (((size_t)(b << 9) + (size_t)i0) << 9);
        float* or1 = out + (((size_t)(b << 9) + (size_t)i1) << 9);
#pragma unroll
        for (int k = 0; k < 16; ++k) {
            float v0 = 0.0f, v1 = 0.0f;
            if (key0[k] >= thr0) {
                float s = key2f(key0[k]);
                v0 = gate / (1.0f + expf(-s));
            }
            if (key1[k] >= thr1) {
                float s = key2f(key1[k]);
                v1 = gate / (1.0f + expf(-s));
            }
            or0[(k << 5) | lane] = v0;   // coalesced: j = k*32 + lane
            or1[(k << 5) | lane] = v1;
        }
    }
}

// ---------------------------------------------------------------------------
extern "C" void kernel_launch(void* const* d_in, const int* in_sizes, int n_in,
                              void* d_out, int out_size) {
    const float* ctx = (const float*)d_in[0];  // context_vec [256,512]
    const float* emb = (const float*)d_in[1];  // var_emb     [512,32]
    const float* W1  = (const float*)d_in[2];  // [32,512]
    const float* b1  = (const float*)d_in[3];  // [32]
    const float* W2  = (const float*)d_in[4];  // [32,32]
    const float* b2  = (const float*)d_in[5];  // [32]
    const float* Wg  = (const float*)d_in[6];  // [1,32]
    const float* bg  = (const float*)d_in[7];  // [1]
    float* out = (float*)d_out;

    cudaFuncSetAttribute(adj_kernel,
                         cudaFuncAttributeMaxDynamicSharedMemorySize, 65536);

    mlp_kernel<<<256, 128>>>(ctx, W1, b1, W2, b2, Wg, bg);
    adj_kernel<<<4096, 128, 65536>>>(emb, out);
}